// round 1
// baseline (speedup 1.0000x reference)
#include <cuda_runtime.h>
#include <string.h>

// ---------------------------------------------------------------------------
// GraphFeatureTokenizer fused kernel for GB300 (sm_103a)
//
//  out_feature[b,t,:] = sum_{j<4} embed[data[tok,j],:]            (token embed)
//                     + eig[src] @ W1 + eig[dst] @ W2             (lap encoder)
//                     + order_weight[src==dst]                    (type embed)
//  masked to 0 for t >= seq_len[b].
//
// Design:
//  - lap_weight (64x768 f32 = 196608 B) cached in dynamic smem as float2.
//  - 256-thread blocks = 4 independent 64-thread groups (named barriers).
//  - Each group processes tiles of TM=8 consecutive slots (same graph since
//    max_len % 8 == 0): gathers ie[8][64] to smem, register-blocked GEMM
//    (acc[8][6] packed f32x2, fma.rn.f32x2), then embed-gather epilogue.
//  - eig table (4 MB) is L2-resident; feature writes use __stcs to avoid
//    evicting the 154 MB embed table from L2.
// ---------------------------------------------------------------------------

#define HID      768
#define HID2     384              // float2 per row
#define MAXLEN   15360
#define NB       8
#define SLOTS    (NB * MAXLEN)    // 122880
#define TM       8
#define NTILES   (SLOTS / TM)     // 15360
#define TPB      256
#define NGRP     4
#define GSZ      64

#define F_ELEMS  (SLOTS * HID)    // 94371840 (feature f32)
#define M_ELEMS  (SLOTS)          // 122880   (mask)
#define I_ELEMS  (SLOTS * 2)      // 245760   (index)

// smem layout (floats): [0,49152) lapW as float2; then ie, meta, offsets
#define SM_W_FLOATS   (64 * HID)              // 49152
#define SM_IE_FLOATS  (NGRP * TM * 64)        // 2048
#define SM_META_INTS  (NGRP * TM * 5)         // 160
#define SM_OFF_INTS   32
#define SMEM_BYTES    ((SM_W_FLOATS + SM_IE_FLOATS) * 4 + (SM_META_INTS + SM_OFF_INTS) * 4)  // 205568

typedef unsigned long long ull;

__device__ __forceinline__ ull pack2(float x) {
    float2 q = make_float2(x, x);
    ull r; memcpy(&r, &q, 8);
    return r;
}
__device__ __forceinline__ float2 unpack2(ull v) {
    float2 r; memcpy(&r, &v, 8);
    return r;
}
__device__ __forceinline__ void fma2(ull& acc, ull a, ull b) {
    asm("fma.rn.f32x2 %0, %1, %2, %0;" : "+l"(acc) : "l"(a), "l"(b));
}

extern "C" __global__ void __launch_bounds__(TPB, 1)
gft_kernel(const float* __restrict__ embedW,
           const float* __restrict__ lapW,
           const float* __restrict__ orderW,
           const float* __restrict__ eig,
           const int*   __restrict__ nodeData,
           const int*   __restrict__ edgeData,
           const int*   __restrict__ edgeIndex,
           const int*   __restrict__ nodeNum,
           const int*   __restrict__ edgeNum,
           float*       __restrict__ out,
           int Etot, int extraMode)
{
    extern __shared__ float smem[];
    float2* sW2  = (float2*)smem;                         // [64][384]
    float*  sIE  = smem + SM_W_FLOATS;                    // [NGRP][TM][64]
    int*    sMeta = (int*)(sIE + SM_IE_FLOATS);           // [NGRP][TM][5]
    int*    sOff  = sMeta + SM_META_INTS;                 // [32]

    const int tid = threadIdx.x;

    // --- init: lapW -> smem, prefix sums of graph sizes ---
    {
        const float4* s = (const float4*)lapW;
        float4* d = (float4*)smem;
        #pragma unroll 4
        for (int i = tid; i < SM_W_FLOATS / 4; i += TPB) d[i] = s[i];
    }
    if (tid < NB) {
        int no = 0, eo = 0;
        for (int x = 0; x < tid; x++) { no += nodeNum[x]; eo += edgeNum[x]; }
        sOff[tid]      = no;
        sOff[8 + tid]  = eo;
        sOff[16 + tid] = nodeNum[tid];
        sOff[24 + tid] = nodeNum[tid] + edgeNum[tid];
    }
    __syncthreads();

    const int g  = tid >> 6;
    const int lt = tid & 63;
    float* gIE   = sIE + g * TM * 64;
    int*   gMeta = sMeta + g * TM * 5;
    const int barid = 1 + g;
    const int grp   = blockIdx.x * NGRP + g;
    const int ngrp  = gridDim.x * NGRP;

    for (int tile = grp; tile < NTILES; tile += ngrp) {
        const int slot0 = tile * TM;
        const int b  = slot0 / MAXLEN;
        const int t0 = slot0 - b * MAXLEN;
        const int nOff = sOff[b], eOff = sOff[8 + b];
        const int nn = sOff[16 + b], seq = sOff[24 + b];

        if (t0 >= seq) {
            // whole tile is padding: zeros + mask/index
            if (lt < TM && extraMode) {
                const int slot = slot0 + lt;
                if (extraMode == 1) {
                    out[(size_t)F_ELEMS + slot] = 1.0f;
                    out[(size_t)F_ELEMS + M_ELEMS + 2 * slot]     = 0.0f;
                    out[(size_t)F_ELEMS + M_ELEMS + 2 * slot + 1] = 0.0f;
                } else {
                    ((unsigned char*)out)[(size_t)F_ELEMS * 4 + slot] = 1;
                    int* ip = (int*)((char*)out + (size_t)F_ELEMS * 4 + M_ELEMS);
                    ip[2 * slot] = 0; ip[2 * slot + 1] = 0;
                }
            }
            const float2 z = make_float2(0.f, 0.f);
            #pragma unroll
            for (int m = 0; m < TM; m++) {
                float2* o2 = (float2*)out + (size_t)(slot0 + m) * HID2;
                #pragma unroll
                for (int i = 0; i < 6; i++) __stcs(&o2[lt + 64 * i], z);
            }
            continue;
        }

        // --- phase A: metadata (lanes 0..7) + ie gather (all 64) ---
        if (lt < TM) {
            const int m = lt, t = t0 + m;
            int r0 = 0, r1 = 0, r2 = 0, r3 = 0, ord = 1, i0 = 0, i1 = 0;
            const bool pad = (t >= seq);
            if (!pad) {
                if (t < nn) {
                    const int gid = nOff + t;
                    int4 rr = ((const int4*)nodeData)[gid];
                    r0 = rr.x; r1 = rr.y; r2 = rr.z; r3 = rr.w;
                    i0 = t; i1 = t; ord = 1;
                } else {
                    const int ge = eOff + (t - nn);
                    int4 rr = ((const int4*)edgeData)[ge];
                    r0 = rr.x; r1 = rr.y; r2 = rr.z; r3 = rr.w;
                    i0 = edgeIndex[ge]; i1 = edgeIndex[Etot + ge];
                    ord = (i0 == i1) ? 1 : 0;
                }
            }
            gMeta[m * 5 + 0] = r0; gMeta[m * 5 + 1] = r1;
            gMeta[m * 5 + 2] = r2; gMeta[m * 5 + 3] = r3;
            gMeta[m * 5 + 4] = ord;
            if (extraMode) {
                const int slot = slot0 + m;
                if (extraMode == 1) {
                    out[(size_t)F_ELEMS + slot] = pad ? 1.0f : 0.0f;
                    out[(size_t)F_ELEMS + M_ELEMS + 2 * slot]     = (float)i0;
                    out[(size_t)F_ELEMS + M_ELEMS + 2 * slot + 1] = (float)i1;
                } else {
                    ((unsigned char*)out)[(size_t)F_ELEMS * 4 + slot] = pad ? 1 : 0;
                    int* ip = (int*)((char*)out + (size_t)F_ELEMS * 4 + M_ELEMS);
                    ip[2 * slot] = i0; ip[2 * slot + 1] = i1;
                }
            }
        }
        {
            // each thread fills 8 consecutive j's of one token's ie[64]
            const int m = lt >> 3;
            const int jbase = (lt & 7) * 8;
            const int t = t0 + m;
            const bool pad = (t >= seq);
            int row = 0;
            if (!pad) {
                if (t < nn) row = nOff + t;
                else {
                    const int ge = eOff + (t - nn);
                    row = nOff + ((jbase < 32) ? edgeIndex[ge] : edgeIndex[Etot + ge]);
                }
            }
            const int jj = jbase & 31;
            const float4* er4 = (const float4*)(eig + (size_t)row * 32 + jj);
            float4 v0, v1;
            if (pad) { v0 = make_float4(0,0,0,0); v1 = v0; }
            else     { v0 = er4[0]; v1 = er4[1]; }
            float4* dst = (float4*)(gIE + m * 64 + jbase);
            dst[0] = v0; dst[1] = v1;
        }
        asm volatile("bar.sync %0, %1;" :: "r"(barid), "r"(GSZ) : "memory");

        // --- phase B: register-blocked GEMM ie[8][64] @ lapW[64][768] ---
        ull acc[TM][6];
        #pragma unroll
        for (int m = 0; m < TM; m++)
            #pragma unroll
            for (int i = 0; i < 6; i++) acc[m][i] = 0ull;

        const float2* gIE2 = (const float2*)gIE;
        #pragma unroll 4
        for (int jp = 0; jp < 32; jp++) {
            ull w0[6], w1[6];
            #pragma unroll
            for (int i = 0; i < 6; i++) {
                w0[i] = *(const ull*)&sW2[(2 * jp)     * HID2 + lt + 64 * i];
                w1[i] = *(const ull*)&sW2[(2 * jp + 1) * HID2 + lt + 64 * i];
            }
            #pragma unroll
            for (int m = 0; m < TM; m++) {
                const float2 p = gIE2[m * 32 + jp];
                const ull xx = pack2(p.x);
                const ull yy = pack2(p.y);
                #pragma unroll
                for (int i = 0; i < 6; i++) {
                    fma2(acc[m][i], xx, w0[i]);
                    fma2(acc[m][i], yy, w1[i]);
                }
            }
        }

        // --- phase C: embed gather + order + store ---
        const float2* em2 = (const float2*)embedW;
        const float2* ow2 = (const float2*)orderW;
        #pragma unroll
        for (int m = 0; m < TM; m++) {
            const int t = t0 + m;
            float2* o2 = (float2*)out + (size_t)(slot0 + m) * HID2;
            if (t >= seq) {
                const float2 z = make_float2(0.f, 0.f);
                #pragma unroll
                for (int i = 0; i < 6; i++) __stcs(&o2[lt + 64 * i], z);
            } else {
                const int r0 = gMeta[m * 5 + 0], r1 = gMeta[m * 5 + 1];
                const int r2 = gMeta[m * 5 + 2], r3 = gMeta[m * 5 + 3];
                const int ord = gMeta[m * 5 + 4];
                const float2* p0 = em2 + (size_t)r0 * HID2;
                const float2* p1 = em2 + (size_t)r1 * HID2;
                const float2* p2 = em2 + (size_t)r2 * HID2;
                const float2* p3 = em2 + (size_t)r3 * HID2;
                const float2* pw = ow2 + (size_t)ord * HID2;
                #pragma unroll
                for (int i = 0; i < 6; i++) {
                    const int h2 = lt + 64 * i;
                    float2 a = unpack2(acc[m][i]);
                    const float2 e0 = p0[h2], e1 = p1[h2], e2 = p2[h2], e3 = p3[h2];
                    const float2 w  = pw[h2];
                    a.x += e0.x + e1.x + e2.x + e3.x + w.x;
                    a.y += e0.y + e1.y + e2.y + e3.y + w.y;
                    __stcs(&o2[h2], a);
                }
            }
        }
        asm volatile("bar.sync %0, %1;" :: "r"(barid), "r"(GSZ) : "memory");
    }
}

extern "C" void kernel_launch(void* const* d_in, const int* in_sizes, int n_in,
                              void* d_out, int out_size)
{
    const float* embedW   = (const float*)d_in[0];
    const float* lapW     = (const float*)d_in[1];
    const float* orderW   = (const float*)d_in[2];
    const float* eig      = (const float*)d_in[3];
    const int*   nodeData = (const int*)d_in[4];
    const int*   edgeData = (const int*)d_in[5];
    const int*   edgeIdx  = (const int*)d_in[6];
    const int*   nodeNum  = (const int*)d_in[7];
    const int*   edgeNum  = (const int*)d_in[8];

    const int Etot = in_sizes[6] / 2;

    // Multi-output layout detection:
    //  mode 1: all three outputs value-cast to f32 and concatenated
    //  mode 2: raw-byte concatenation (mask as u8, index as i32) viewed as f32
    //  mode 0: feature only
    int extraMode = 0;
    const long long allF  = (long long)F_ELEMS + M_ELEMS + I_ELEMS;          // 94740480
    const long long rawB  = (long long)F_ELEMS + (M_ELEMS + I_ELEMS * 4) / 4; // 94648320
    if ((long long)out_size == allF)      extraMode = 1;
    else if ((long long)out_size == rawB) extraMode = 2;

    cudaFuncSetAttribute(gft_kernel, cudaFuncAttributeMaxDynamicSharedMemorySize, SMEM_BYTES);
    gft_kernel<<<152, TPB, SMEM_BYTES>>>(embedW, lapW, orderW, eig,
                                         nodeData, edgeData, edgeIdx,
                                         nodeNum, edgeNum,
                                         (float*)d_out, Etot, extraMode);
}

// round 2
// speedup vs baseline: 1.2572x; 1.2572x over previous
#include <cuda_runtime.h>
#include <string.h>

// ---------------------------------------------------------------------------
// GraphFeatureTokenizer fused kernel for GB300 (sm_103a) — Round 2
//
// R1 was latency-bound (occ 12.3%: 205KB smem -> 1 CTA/SM -> 8 warps).
// R2: split the 768-d hidden dimension into 3 slices of 256 cols. Each CTA
// caches only its 64x256 f32 slice of lap_weight (64KB smem) -> 3 CTAs/SM
// -> 24 warps/SM. Metadata/eig gathers duplicate x3 (cheap, L2-resident).
// DRAM bytes unchanged. Packed fma.rn.f32x2 GEMM, TM=8 token tiles,
// 64-thread groups with named barriers, __stcs streaming stores.
// ---------------------------------------------------------------------------

#define HID      768
#define HID2     384              // float2 per row
#define NSPLIT   3
#define SCOLS    256              // cols per split
#define SCOLS2   128              // float2 per split
#define MAXLEN   15360
#define NB       8
#define SLOTS    (NB * MAXLEN)    // 122880
#define TM       8
#define NTILES   (SLOTS / TM)     // 15360
#define TPB      256
#define NGRP     4
#define GSZ      64
#define NWORK    152              // worker CTAs per split (one per SM)

#define F_ELEMS  (SLOTS * HID)    // 94371840 (feature f32)
#define M_ELEMS  (SLOTS)          // 122880   (mask)
#define I_ELEMS  (SLOTS * 2)      // 245760   (index)

// smem (floats): [0, 64*256) weight slice; then ie, meta, offsets
#define SM_W_FLOATS   (64 * SCOLS)            // 16384 floats = 64KB
#define SM_IE_FLOATS  (NGRP * TM * 64)        // 2048
#define SM_META_INTS  (NGRP * TM * 5)         // 160
#define SM_OFF_INTS   32
#define SMEM_BYTES    ((SM_W_FLOATS + SM_IE_FLOATS) * 4 + (SM_META_INTS + SM_OFF_INTS) * 4)

typedef unsigned long long ull;

__device__ __forceinline__ ull pack2(float x) {
    float2 q = make_float2(x, x);
    ull r; memcpy(&r, &q, 8);
    return r;
}
__device__ __forceinline__ float2 unpack2(ull v) {
    float2 r; memcpy(&r, &v, 8);
    return r;
}
__device__ __forceinline__ void fma2(ull& acc, ull a, ull b) {
    asm("fma.rn.f32x2 %0, %1, %2, %0;" : "+l"(acc) : "l"(a), "l"(b));
}

extern "C" __global__ void __launch_bounds__(TPB, 3)
gft_kernel(const float* __restrict__ embedW,
           const float* __restrict__ lapW,
           const float* __restrict__ orderW,
           const float* __restrict__ eig,
           const int*   __restrict__ nodeData,
           const int*   __restrict__ edgeData,
           const int*   __restrict__ edgeIndex,
           const int*   __restrict__ nodeNum,
           const int*   __restrict__ edgeNum,
           float*       __restrict__ out,
           int Etot, int extraMode)
{
    extern __shared__ float smem[];
    float2* sW2  = (float2*)smem;                         // [64][SCOLS2]
    float*  sIE  = smem + SM_W_FLOATS;                    // [NGRP][TM][64]
    int*    sMeta = (int*)(sIE + SM_IE_FLOATS);           // [NGRP][TM][5]
    int*    sOff  = sMeta + SM_META_INTS;                 // [32]

    const int tid    = threadIdx.x;
    const int nwork  = gridDim.x / NSPLIT;
    const int split  = blockIdx.x / nwork;                // 0..2
    const int worker = blockIdx.x - split * nwork;

    // --- init: weight slice -> smem, prefix sums of graph sizes ---
    {
        // slice cols [split*256, split*256+256): 64 float4 per row
        const float4* s = (const float4*)lapW;
        float4* d = (float4*)smem;
        #pragma unroll 4
        for (int i = tid; i < 64 * (SCOLS / 4); i += TPB) {
            const int r = i >> 6, c4 = i & 63;
            d[i] = s[r * (HID / 4) + split * (SCOLS / 4) + c4];
        }
    }
    if (tid < NB) {
        int no = 0, eo = 0;
        for (int x = 0; x < tid; x++) { no += nodeNum[x]; eo += edgeNum[x]; }
        sOff[tid]      = no;
        sOff[8 + tid]  = eo;
        sOff[16 + tid] = nodeNum[tid];
        sOff[24 + tid] = nodeNum[tid] + edgeNum[tid];
    }
    __syncthreads();

    const int g  = tid >> 6;
    const int lt = tid & 63;
    float* gIE   = sIE + g * TM * 64;
    int*   gMeta = sMeta + g * TM * 5;
    const int barid = 1 + g;
    const int grp   = worker * NGRP + g;
    const int ngrp  = nwork * NGRP;
    const int colbase2 = split * SCOLS2;                  // float2 col offset

    for (int tile = grp; tile < NTILES; tile += ngrp) {
        const int slot0 = tile * TM;
        const int b  = slot0 / MAXLEN;
        const int t0 = slot0 - b * MAXLEN;
        const int nOff = sOff[b], eOff = sOff[8 + b];
        const int nn = sOff[16 + b], seq = sOff[24 + b];

        if (t0 >= seq) {
            // whole tile is padding: zeros (this split's cols) + mask/index
            if (split == 0 && lt < TM && extraMode) {
                const int slot = slot0 + lt;
                if (extraMode == 1) {
                    out[(size_t)F_ELEMS + slot] = 1.0f;
                    out[(size_t)F_ELEMS + M_ELEMS + 2 * slot]     = 0.0f;
                    out[(size_t)F_ELEMS + M_ELEMS + 2 * slot + 1] = 0.0f;
                } else {
                    ((unsigned char*)out)[(size_t)F_ELEMS * 4 + slot] = 1;
                    int* ip = (int*)((char*)out + (size_t)F_ELEMS * 4 + M_ELEMS);
                    ip[2 * slot] = 0; ip[2 * slot + 1] = 0;
                }
            }
            const float2 z = make_float2(0.f, 0.f);
            #pragma unroll
            for (int m = 0; m < TM; m++) {
                float2* o2 = (float2*)out + (size_t)(slot0 + m) * HID2 + colbase2;
                #pragma unroll
                for (int i = 0; i < 2; i++) __stcs(&o2[lt + 64 * i], z);
            }
            continue;
        }

        // --- phase A: metadata (lanes 0..7) + ie gather (all 64) ---
        if (lt < TM) {
            const int m = lt, t = t0 + m;
            int r0 = 0, r1 = 0, r2 = 0, r3 = 0, ord = 1, i0 = 0, i1 = 0;
            const bool pad = (t >= seq);
            if (!pad) {
                if (t < nn) {
                    const int gid = nOff + t;
                    int4 rr = ((const int4*)nodeData)[gid];
                    r0 = rr.x; r1 = rr.y; r2 = rr.z; r3 = rr.w;
                    i0 = t; i1 = t; ord = 1;
                } else {
                    const int ge = eOff + (t - nn);
                    int4 rr = ((const int4*)edgeData)[ge];
                    r0 = rr.x; r1 = rr.y; r2 = rr.z; r3 = rr.w;
                    i0 = edgeIndex[ge]; i1 = edgeIndex[Etot + ge];
                    ord = (i0 == i1) ? 1 : 0;
                }
            }
            gMeta[m * 5 + 0] = r0; gMeta[m * 5 + 1] = r1;
            gMeta[m * 5 + 2] = r2; gMeta[m * 5 + 3] = r3;
            gMeta[m * 5 + 4] = ord;
            if (split == 0 && extraMode) {
                const int slot = slot0 + m;
                if (extraMode == 1) {
                    out[(size_t)F_ELEMS + slot] = pad ? 1.0f : 0.0f;
                    out[(size_t)F_ELEMS + M_ELEMS + 2 * slot]     = (float)i0;
                    out[(size_t)F_ELEMS + M_ELEMS + 2 * slot + 1] = (float)i1;
                } else {
                    ((unsigned char*)out)[(size_t)F_ELEMS * 4 + slot] = pad ? 1 : 0;
                    int* ip = (int*)((char*)out + (size_t)F_ELEMS * 4 + M_ELEMS);
                    ip[2 * slot] = i0; ip[2 * slot + 1] = i1;
                }
            }
        }
        {
            // each thread fills 8 consecutive j's of one token's ie[64]
            const int m = lt >> 3;
            const int jbase = (lt & 7) * 8;
            const int t = t0 + m;
            const bool pad = (t >= seq);
            int row = 0;
            if (!pad) {
                if (t < nn) row = nOff + t;
                else {
                    const int ge = eOff + (t - nn);
                    row = nOff + ((jbase < 32) ? edgeIndex[ge] : edgeIndex[Etot + ge]);
                }
            }
            const int jj = jbase & 31;
            const float4* er4 = (const float4*)(eig + (size_t)row * 32 + jj);
            float4 v0, v1;
            if (pad) { v0 = make_float4(0,0,0,0); v1 = v0; }
            else     { v0 = er4[0]; v1 = er4[1]; }
            float4* dst = (float4*)(gIE + m * 64 + jbase);
            dst[0] = v0; dst[1] = v1;
        }
        asm volatile("bar.sync %0, %1;" :: "r"(barid), "r"(GSZ) : "memory");

        // --- phase B: GEMM ie[8][64] @ Wslice[64][256] ---
        ull acc[TM][2];
        #pragma unroll
        for (int m = 0; m < TM; m++) { acc[m][0] = 0ull; acc[m][1] = 0ull; }

        const float2* gIE2 = (const float2*)gIE;
        #pragma unroll 4
        for (int jp = 0; jp < 32; jp++) {
            ull w0[2], w1[2];
            #pragma unroll
            for (int i = 0; i < 2; i++) {
                w0[i] = *(const ull*)&sW2[(2 * jp)     * SCOLS2 + lt + 64 * i];
                w1[i] = *(const ull*)&sW2[(2 * jp + 1) * SCOLS2 + lt + 64 * i];
            }
            #pragma unroll
            for (int m = 0; m < TM; m++) {
                const float2 p = gIE2[m * 32 + jp];
                const ull xx = pack2(p.x);
                const ull yy = pack2(p.y);
                #pragma unroll
                for (int i = 0; i < 2; i++) {
                    fma2(acc[m][i], xx, w0[i]);
                    fma2(acc[m][i], yy, w1[i]);
                }
            }
        }

        // --- phase C: embed gather + order + store (this split's cols) ---
        const float2* em2 = (const float2*)embedW + colbase2;
        const float2* ow2 = (const float2*)orderW + colbase2;
        #pragma unroll
        for (int m = 0; m < TM; m++) {
            const int t = t0 + m;
            float2* o2 = (float2*)out + (size_t)(slot0 + m) * HID2 + colbase2;
            if (t >= seq) {
                const float2 z = make_float2(0.f, 0.f);
                #pragma unroll
                for (int i = 0; i < 2; i++) __stcs(&o2[lt + 64 * i], z);
            } else {
                const int r0 = gMeta[m * 5 + 0], r1 = gMeta[m * 5 + 1];
                const int r2 = gMeta[m * 5 + 2], r3 = gMeta[m * 5 + 3];
                const int ord = gMeta[m * 5 + 4];
                const float2* p0 = em2 + (size_t)r0 * HID2;
                const float2* p1 = em2 + (size_t)r1 * HID2;
                const float2* p2 = em2 + (size_t)r2 * HID2;
                const float2* p3 = em2 + (size_t)r3 * HID2;
                const float2* pw = ow2 + (size_t)ord * HID2;
                #pragma unroll
                for (int i = 0; i < 2; i++) {
                    const int h2 = lt + 64 * i;
                    float2 a = unpack2(acc[m][i]);
                    const float2 e0 = p0[h2], e1 = p1[h2], e2 = p2[h2], e3 = p3[h2];
                    const float2 w  = pw[h2];
                    a.x += e0.x + e1.x + e2.x + e3.x + w.x;
                    a.y += e0.y + e1.y + e2.y + e3.y + w.y;
                    __stcs(&o2[h2], a);
                }
            }
        }
        asm volatile("bar.sync %0, %1;" :: "r"(barid), "r"(GSZ) : "memory");
    }
}

extern "C" void kernel_launch(void* const* d_in, const int* in_sizes, int n_in,
                              void* d_out, int out_size)
{
    const float* embedW   = (const float*)d_in[0];
    const float* lapW     = (const float*)d_in[1];
    const float* orderW   = (const float*)d_in[2];
    const float* eig      = (const float*)d_in[3];
    const int*   nodeData = (const int*)d_in[4];
    const int*   edgeData = (const int*)d_in[5];
    const int*   edgeIdx  = (const int*)d_in[6];
    const int*   nodeNum  = (const int*)d_in[7];
    const int*   edgeNum  = (const int*)d_in[8];

    const int Etot = in_sizes[6] / 2;

    // Multi-output layout detection (same as R1, which passed):
    int extraMode = 0;
    const long long allF  = (long long)F_ELEMS + M_ELEMS + I_ELEMS;           // 94740480
    const long long rawB  = (long long)F_ELEMS + (M_ELEMS + I_ELEMS * 4) / 4; // 94648320
    if ((long long)out_size == allF)      extraMode = 1;
    else if ((long long)out_size == rawB) extraMode = 2;

    cudaFuncSetAttribute(gft_kernel, cudaFuncAttributeMaxDynamicSharedMemorySize, SMEM_BYTES);
    gft_kernel<<<NWORK * NSPLIT, TPB, SMEM_BYTES>>>(embedW, lapW, orderW, eig,
                                                    nodeData, edgeData, edgeIdx,
                                                    nodeNum, edgeNum,
                                                    (float*)d_out, Etot, extraMode);
}

// round 3
// speedup vs baseline: 1.3800x; 1.0976x over previous
#include <cuda_runtime.h>
#include <string.h>

// ---------------------------------------------------------------------------
// GraphFeatureTokenizer fused kernel for GB300 (sm_103a) — Round 3
//
// R2 was latency-bound on embed-table DRAM gathers (issue 37%, L1 61%).
// R3: (a) prefetch.global.L2 of each tile's embed rows during phase A so the
// DRAM latency hides under the GEMM; (b) thread owns 4 consecutive f32 cols
// so all smem/global accesses become 128-bit (halves LDS/LDG issue count and
// ie crossbar cycles); (c) __stcs streaming stores preserved so the output
// stream doesn't evict prefetched embed lines from L2.
// 3 splits of 256 cols, 3 CTAs/SM, TM=8 token tiles, fma.rn.f32x2 GEMM.
// ---------------------------------------------------------------------------

#define HID      768
#define HID4     192              // float4 per row
#define NSPLIT   3
#define SCOLS    256              // cols per split
#define SCOLS4   64               // float4 per split
#define MAXLEN   15360
#define NB       8
#define SLOTS    (NB * MAXLEN)    // 122880
#define TM       8
#define NTILES   (SLOTS / TM)     // 15360
#define TPB      256
#define NGRP     4
#define GSZ      64
#define NWORK    152

#define F_ELEMS  (SLOTS * HID)    // 94371840
#define M_ELEMS  (SLOTS)          // 122880
#define I_ELEMS  (SLOTS * 2)      // 245760

#define SM_W_FLOATS   (64 * SCOLS)            // 16384 floats = 64KB
#define SM_IE_FLOATS  (NGRP * TM * 64)        // 2048
#define SM_META_INTS  (NGRP * TM * 5)         // 160
#define SM_OFF_INTS   32
#define SMEM_BYTES    ((SM_W_FLOATS + SM_IE_FLOATS) * 4 + (SM_META_INTS + SM_OFF_INTS) * 4)

typedef unsigned long long ull;

__device__ __forceinline__ ull pack2(float x) {
    float2 q = make_float2(x, x);
    ull r; memcpy(&r, &q, 8);
    return r;
}
__device__ __forceinline__ float2 unpack2(ull v) {
    float2 r; memcpy(&r, &v, 8);
    return r;
}
__device__ __forceinline__ ull lo2(float4 w) {
    float2 q = make_float2(w.x, w.y);
    ull r; memcpy(&r, &q, 8);
    return r;
}
__device__ __forceinline__ ull hi2(float4 w) {
    float2 q = make_float2(w.z, w.w);
    ull r; memcpy(&r, &q, 8);
    return r;
}
__device__ __forceinline__ void fma2(ull& acc, ull a, ull b) {
    asm("fma.rn.f32x2 %0, %1, %2, %0;" : "+l"(acc) : "l"(a), "l"(b));
}
__device__ __forceinline__ void pf_l2(const void* p) {
    asm volatile("prefetch.global.L2 [%0];" :: "l"(p));
}

extern "C" __global__ void __launch_bounds__(TPB, 3)
gft_kernel(const float* __restrict__ embedW,
           const float* __restrict__ lapW,
           const float* __restrict__ orderW,
           const float* __restrict__ eig,
           const int*   __restrict__ nodeData,
           const int*   __restrict__ edgeData,
           const int*   __restrict__ edgeIndex,
           const int*   __restrict__ nodeNum,
           const int*   __restrict__ edgeNum,
           float*       __restrict__ out,
           int Etot, int extraMode)
{
    extern __shared__ float smem[];
    float4* sW4  = (float4*)smem;                         // [64 rows][SCOLS4]
    float*  sIE  = smem + SM_W_FLOATS;                    // [NGRP][TM][64]
    int*    sMeta = (int*)(sIE + SM_IE_FLOATS);           // [NGRP][TM][5]
    int*    sOff  = sMeta + SM_META_INTS;                 // [32]

    const int tid    = threadIdx.x;
    const int nwork  = gridDim.x / NSPLIT;
    const int split  = blockIdx.x / nwork;                // 0..2
    const int worker = blockIdx.x - split * nwork;

    // --- init: weight slice -> smem (natural layout), prefix sums ---
    {
        const float4* s = (const float4*)lapW;
        #pragma unroll 4
        for (int i = tid; i < 64 * SCOLS4; i += TPB) {
            const int k = i >> 6, c4 = i & 63;
            sW4[i] = s[k * HID4 + split * SCOLS4 + c4];
        }
    }
    if (tid < NB) {
        int no = 0, eo = 0;
        for (int x = 0; x < tid; x++) { no += nodeNum[x]; eo += edgeNum[x]; }
        sOff[tid]      = no;
        sOff[8 + tid]  = eo;
        sOff[16 + tid] = nodeNum[tid];
        sOff[24 + tid] = nodeNum[tid] + edgeNum[tid];
    }
    __syncthreads();

    const int g  = tid >> 6;
    const int lt = tid & 63;
    float* gIE   = sIE + g * TM * 64;
    int*   gMeta = sMeta + g * TM * 5;
    const int barid = 1 + g;
    const int grp   = worker * NGRP + g;
    const int ngrp  = nwork * NGRP;
    const int cb4   = split * SCOLS4 + lt;                // this thread's float4 col

    for (int tile = grp; tile < NTILES; tile += ngrp) {
        const int slot0 = tile * TM;
        const int b  = slot0 / MAXLEN;
        const int t0 = slot0 - b * MAXLEN;
        const int nOff = sOff[b], eOff = sOff[8 + b];
        const int nn = sOff[16 + b], seq = sOff[24 + b];

        if (t0 >= seq) {
            if (split == 0 && lt < TM && extraMode) {
                const int slot = slot0 + lt;
                if (extraMode == 1) {
                    out[(size_t)F_ELEMS + slot] = 1.0f;
                    out[(size_t)F_ELEMS + M_ELEMS + 2 * slot]     = 0.0f;
                    out[(size_t)F_ELEMS + M_ELEMS + 2 * slot + 1] = 0.0f;
                } else {
                    ((unsigned char*)out)[(size_t)F_ELEMS * 4 + slot] = 1;
                    int* ip = (int*)((char*)out + (size_t)F_ELEMS * 4 + M_ELEMS);
                    ip[2 * slot] = 0; ip[2 * slot + 1] = 0;
                }
            }
            const float4 z = make_float4(0.f, 0.f, 0.f, 0.f);
            #pragma unroll
            for (int m = 0; m < TM; m++)
                __stcs((float4*)out + (size_t)(slot0 + m) * HID4 + cb4, z);
            continue;
        }

        // --- phase A: metadata (lanes 0..7), embed L2 prefetch + ie gather ---
        if (lt < TM) {
            const int m = lt, t = t0 + m;
            int r0 = 0, r1 = 0, r2 = 0, r3 = 0, ord = 1, i0 = 0, i1 = 0;
            const bool pad = (t >= seq);
            if (!pad) {
                if (t < nn) {
                    int4 rr = ((const int4*)nodeData)[nOff + t];
                    r0 = rr.x; r1 = rr.y; r2 = rr.z; r3 = rr.w;
                    i0 = t; i1 = t; ord = 1;
                } else {
                    const int ge = eOff + (t - nn);
                    int4 rr = ((const int4*)edgeData)[ge];
                    r0 = rr.x; r1 = rr.y; r2 = rr.z; r3 = rr.w;
                    i0 = edgeIndex[ge]; i1 = edgeIndex[Etot + ge];
                    ord = (i0 == i1) ? 1 : 0;
                }
            }
            gMeta[m * 5 + 0] = r0; gMeta[m * 5 + 1] = r1;
            gMeta[m * 5 + 2] = r2; gMeta[m * 5 + 3] = r3;
            gMeta[m * 5 + 4] = ord;
            if (split == 0 && extraMode) {
                const int slot = slot0 + m;
                if (extraMode == 1) {
                    out[(size_t)F_ELEMS + slot] = pad ? 1.0f : 0.0f;
                    out[(size_t)F_ELEMS + M_ELEMS + 2 * slot]     = (float)i0;
                    out[(size_t)F_ELEMS + M_ELEMS + 2 * slot + 1] = (float)i1;
                } else {
                    ((unsigned char*)out)[(size_t)F_ELEMS * 4 + slot] = pad ? 1 : 0;
                    int* ip = (int*)((char*)out + (size_t)F_ELEMS * 4 + M_ELEMS);
                    ip[2 * slot] = i0; ip[2 * slot + 1] = i1;
                }
            }
        }
        {
            // L2 prefetch: thread (m = lt>>3, j = lt&7) prefetches 128B line j
            // of all 4 embed rows of token m (covers the 1KB split slice).
            const int m = lt >> 3, j = lt & 7;
            const int t = t0 + m;
            if (t < seq) {
                int4 rr;
                if (t < nn) rr = ((const int4*)nodeData)[nOff + t];
                else        rr = ((const int4*)edgeData)[eOff + (t - nn)];
                const char* eb = (const char*)embedW + (size_t)split * 1024 + j * 128;
                pf_l2(eb + (size_t)rr.x * 3072);
                pf_l2(eb + (size_t)rr.y * 3072);
                pf_l2(eb + (size_t)rr.z * 3072);
                pf_l2(eb + (size_t)rr.w * 3072);
            }
        }
        {
            // ie gather: thread fills 8 consecutive j's of one token's ie[64]
            const int m = lt >> 3;
            const int jbase = (lt & 7) * 8;
            const int t = t0 + m;
            const bool pad = (t >= seq);
            int row = 0;
            if (!pad) {
                if (t < nn) row = nOff + t;
                else {
                    const int ge = eOff + (t - nn);
                    row = nOff + ((jbase < 32) ? edgeIndex[ge] : edgeIndex[Etot + ge]);
                }
            }
            const int jj = jbase & 31;
            const float4* er4 = (const float4*)(eig + (size_t)row * 32 + jj);
            float4 v0, v1;
            if (pad) { v0 = make_float4(0,0,0,0); v1 = v0; }
            else     { v0 = er4[0]; v1 = er4[1]; }
            float4* dst = (float4*)(gIE + m * 64 + jbase);
            dst[0] = v0; dst[1] = v1;
        }
        asm volatile("bar.sync %0, %1;" :: "r"(barid), "r"(GSZ) : "memory");

        // --- phase B: GEMM ie[8][64] @ Wslice[64][256], all-128-bit LDS ---
        ull acc[TM][2];
        #pragma unroll
        for (int m = 0; m < TM; m++) { acc[m][0] = 0ull; acc[m][1] = 0ull; }

        #pragma unroll 2
        for (int kq = 0; kq < 16; kq++) {           // quad of K rows
            float4 w0 = sW4[(4 * kq + 0) * SCOLS4 + lt];
            float4 w1 = sW4[(4 * kq + 1) * SCOLS4 + lt];
            float4 w2 = sW4[(4 * kq + 2) * SCOLS4 + lt];
            float4 w3 = sW4[(4 * kq + 3) * SCOLS4 + lt];
            const ull w0l = lo2(w0), w0h = hi2(w0);
            const ull w1l = lo2(w1), w1h = hi2(w1);
            const ull w2l = lo2(w2), w2h = hi2(w2);
            const ull w3l = lo2(w3), w3h = hi2(w3);
            #pragma unroll
            for (int m = 0; m < TM; m++) {
                const float4 p = ((const float4*)(gIE + m * 64))[kq];
                const ull x0 = pack2(p.x), x1 = pack2(p.y);
                const ull x2 = pack2(p.z), x3 = pack2(p.w);
                fma2(acc[m][0], x0, w0l); fma2(acc[m][1], x0, w0h);
                fma2(acc[m][0], x1, w1l); fma2(acc[m][1], x1, w1h);
                fma2(acc[m][0], x2, w2l); fma2(acc[m][1], x2, w2h);
                fma2(acc[m][0], x3, w3l); fma2(acc[m][1], x3, w3h);
            }
        }

        // --- phase C: embed gather (L2-hot) + order + store, all 128-bit ---
        const float4* em4 = (const float4*)embedW;
        const float4* ow4 = (const float4*)orderW;
        #pragma unroll
        for (int m = 0; m < TM; m++) {
            const int t = t0 + m;
            float4* o4 = (float4*)out + (size_t)(slot0 + m) * HID4 + cb4;
            if (t >= seq) {
                __stcs(o4, make_float4(0.f, 0.f, 0.f, 0.f));
            } else {
                const int r0 = gMeta[m * 5 + 0], r1 = gMeta[m * 5 + 1];
                const int r2 = gMeta[m * 5 + 2], r3 = gMeta[m * 5 + 3];
                const int ord = gMeta[m * 5 + 4];
                const float4 e0 = em4[(size_t)r0 * HID4 + cb4];
                const float4 e1 = em4[(size_t)r1 * HID4 + cb4];
                const float4 e2 = em4[(size_t)r2 * HID4 + cb4];
                const float4 e3 = em4[(size_t)r3 * HID4 + cb4];
                const float4 w  = ow4[(size_t)ord * HID4 + cb4];
                const float2 a0 = unpack2(acc[m][0]);
                const float2 a1 = unpack2(acc[m][1]);
                float4 v;
                v.x = a0.x + e0.x + e1.x + e2.x + e3.x + w.x;
                v.y = a0.y + e0.y + e1.y + e2.y + e3.y + w.y;
                v.z = a1.x + e0.z + e1.z + e2.z + e3.z + w.z;
                v.w = a1.y + e0.w + e1.w + e2.w + e3.w + w.w;
                __stcs(o4, v);
            }
        }
        asm volatile("bar.sync %0, %1;" :: "r"(barid), "r"(GSZ) : "memory");
    }
}

extern "C" void kernel_launch(void* const* d_in, const int* in_sizes, int n_in,
                              void* d_out, int out_size)
{
    const float* embedW   = (const float*)d_in[0];
    const float* lapW     = (const float*)d_in[1];
    const float* orderW   = (const float*)d_in[2];
    const float* eig      = (const float*)d_in[3];
    const int*   nodeData = (const int*)d_in[4];
    const int*   edgeData = (const int*)d_in[5];
    const int*   edgeIdx  = (const int*)d_in[6];
    const int*   nodeNum  = (const int*)d_in[7];
    const int*   edgeNum  = (const int*)d_in[8];

    const int Etot = in_sizes[6] / 2;

    int extraMode = 0;
    const long long allF  = (long long)F_ELEMS + M_ELEMS + I_ELEMS;           // 94740480
    const long long rawB  = (long long)F_ELEMS + (M_ELEMS + I_ELEMS * 4) / 4; // 94648320
    if ((long long)out_size == allF)      extraMode = 1;
    else if ((long long)out_size == rawB) extraMode = 2;

    cudaFuncSetAttribute(gft_kernel, cudaFuncAttributeMaxDynamicSharedMemorySize, SMEM_BYTES);
    gft_kernel<<<NWORK * NSPLIT, TPB, SMEM_BYTES>>>(embedW, lapW, orderW, eig,
                                                    nodeData, edgeData, edgeIdx,
                                                    nodeNum, edgeNum,
                                                    (float*)d_out, Etot, extraMode);
}